// round 3
// baseline (speedup 1.0000x reference)
#include <cuda_runtime.h>
#include <cstdint>

// ---------------------------------------------------------------------------
// Residual MLP block, sm_103 baseline-PTX path (no tcgen05 — harness compiles
// at compute_103 virtual arch, so only sm_80/sm_90 baseline features compile).
// GEMMs via mma.sync m16n8k8 tf32 + cp.async 4-stage pipeline.
// out = x + W2 @ gelu(W1 @ LN(x) + b1) + b2
// x [16384,1024] fp32, W [1024,1024] row-major [out,in] (K-major "B").
// ---------------------------------------------------------------------------

#define ROWS   16384
#define WID    1024
#define BM     128
#define BN     128
#define BK     16
#define NITER  (WID / BK)        // 64
#define STAGES 4
#define ASTRIDE 20               // floats per row in smem (pad 16 -> 20, 80B: 16B-aligned, conflict-free)
#define STAGE_F (BM * ASTRIDE)   // 2560 floats per stage per operand

// scratch (device globals: allocation-free per harness rules)
__device__ float g_ln[ROWS * WID];
__device__ float g_h [ROWS * WID];
__device__ float g_w1[WID * WID];
__device__ float g_w2[WID * WID];

// ---------------------------------------------------------------------------
static __device__ __forceinline__ uint32_t smem_u32(const void* p) {
    uint32_t a;
    asm("{ .reg .u64 t; cvta.to.shared.u64 t, %1; cvt.u32.u64 %0, t; }"
        : "=r"(a) : "l"(p));
    return a;
}

static __device__ __forceinline__ float tf32_rna(float f) {
    uint32_t r;
    asm("cvt.rna.tf32.f32 %0, %1;" : "=r"(r) : "f"(f));
    return __uint_as_float(r);
}

static __device__ __forceinline__ void cp_async16(uint32_t saddr, const void* g) {
    asm volatile("cp.async.ca.shared.global [%0], [%1], 16;"
                 :: "r"(saddr), "l"(g) : "memory");
}
#define CP_COMMIT()  asm volatile("cp.async.commit_group;" ::: "memory")
#define CP_WAIT(N)   asm volatile("cp.async.wait_group %0;" :: "n"(N) : "memory")

static __device__ __forceinline__ void mma_tf32(float& c0, float& c1, float& c2, float& c3,
                                                uint32_t a0, uint32_t a1, uint32_t a2, uint32_t a3,
                                                uint32_t b0, uint32_t b1) {
    asm volatile("mma.sync.aligned.m16n8k8.row.col.f32.tf32.tf32.f32 "
                 "{%0,%1,%2,%3}, {%4,%5,%6,%7}, {%8,%9}, {%0,%1,%2,%3};"
                 : "+f"(c0), "+f"(c1), "+f"(c2), "+f"(c3)
                 : "r"(a0), "r"(a1), "r"(a2), "r"(a3), "r"(b0), "r"(b1));
}

static __device__ __forceinline__ float gelu_exact(float v) {
    return 0.5f * v * (1.0f + erff(v * 0.7071067811865476f));
}

// ---------------------------------------------------------------------------
// Round weights to tf32 (RNA) so HW truncation in the MMA is exact.
// ---------------------------------------------------------------------------
__global__ void rw_kernel(const float* __restrict__ w, float* __restrict__ o) {
    int i = blockIdx.x * blockDim.x + threadIdx.x;   // over float4
    float4 v = reinterpret_cast<const float4*>(w)[i];
    v.x = tf32_rna(v.x); v.y = tf32_rna(v.y); v.z = tf32_rna(v.z); v.w = tf32_rna(v.w);
    reinterpret_cast<float4*>(o)[i] = v;
}

// ---------------------------------------------------------------------------
// LayerNorm, output rounded to tf32 (RNA). One 128-thread block per row.
// ---------------------------------------------------------------------------
__global__ void ln_kernel(const float* __restrict__ x, const float* __restrict__ g,
                          const float* __restrict__ b, float* __restrict__ o) {
    int row = blockIdx.x;
    int t   = threadIdx.x;
    int wid = t >> 5, lid = t & 31;
    const float4* xr = reinterpret_cast<const float4*>(x + (size_t)row * WID);
    float4 v0 = xr[t], v1 = xr[t + 128];

    float s = v0.x + v0.y + v0.z + v0.w + v1.x + v1.y + v1.z + v1.w;
    float q = v0.x*v0.x + v0.y*v0.y + v0.z*v0.z + v0.w*v0.w
            + v1.x*v1.x + v1.y*v1.y + v1.z*v1.z + v1.w*v1.w;
    #pragma unroll
    for (int off = 16; off > 0; off >>= 1) {
        s += __shfl_xor_sync(0xffffffffu, s, off);
        q += __shfl_xor_sync(0xffffffffu, q, off);
    }
    __shared__ float rs_[4], rq_[4];
    if (lid == 0) { rs_[wid] = s; rq_[wid] = q; }
    __syncthreads();
    float S  = rs_[0] + rs_[1] + rs_[2] + rs_[3];
    float Q  = rq_[0] + rq_[1] + rq_[2] + rq_[3];
    float mu = S * (1.0f / WID);
    float var = Q * (1.0f / WID) - mu * mu;
    float r  = rsqrtf(var + 1e-5f);

    const float4* gr = reinterpret_cast<const float4*>(g);
    const float4* br = reinterpret_cast<const float4*>(b);
    float4 g0 = gr[t], g1 = gr[t + 128], b0 = br[t], b1 = br[t + 128];
    float4 o0, o1;
    o0.x = tf32_rna((v0.x - mu) * r * g0.x + b0.x);
    o0.y = tf32_rna((v0.y - mu) * r * g0.y + b0.y);
    o0.z = tf32_rna((v0.z - mu) * r * g0.z + b0.z);
    o0.w = tf32_rna((v0.w - mu) * r * g0.w + b0.w);
    o1.x = tf32_rna((v1.x - mu) * r * g1.x + b1.x);
    o1.y = tf32_rna((v1.y - mu) * r * g1.y + b1.y);
    o1.z = tf32_rna((v1.z - mu) * r * g1.z + b1.z);
    o1.w = tf32_rna((v1.w - mu) * r * g1.w + b1.w);
    float4* orow = reinterpret_cast<float4*>(o + (size_t)row * WID);
    orow[t] = o0; orow[t + 128] = o1;
}

// ---------------------------------------------------------------------------
// GEMM: D[BM,BN] = A[BM,K] @ B[BN,K]^T (+bias, +gelu | +residual)
// 256 threads = 8 warps, warp tile 64x32 (layout 2m x 4n).
// ---------------------------------------------------------------------------
template <bool DO_GELU>
__global__ void __launch_bounds__(256) gemm_kernel(
    const float* __restrict__ A, const float* __restrict__ B,
    const float* __restrict__ bias, const float* __restrict__ resid,
    float* __restrict__ outp)
{
    extern __shared__ float smem[];
    float* As = smem;
    float* Bs = smem + STAGES * STAGE_F;

    const int tid    = threadIdx.x;
    const int lane   = tid & 31;
    const int w      = tid >> 5;
    const int warp_m = (w & 1) * 64;
    const int warp_n = (w >> 1) * 32;
    const int m0     = blockIdx.x * BM;
    const int n0     = blockIdx.y * BN;

    // per-thread cp.async assignments: 2 chunks of 16B for A and for B per stage
    const int row_c0 = tid >> 2;            // chunk 0: row tid/4
    const int kc0    = (tid & 3) * 4;       // k offset (floats)
    const int row_c1 = (tid + 256) >> 2;    // chunk 1
    const int kc1    = kc0;

    float c[4][4][4];
    #pragma unroll
    for (int mi = 0; mi < 4; mi++)
        #pragma unroll
        for (int ni = 0; ni < 4; ni++)
            #pragma unroll
            for (int r = 0; r < 4; r++) c[mi][ni][r] = 0.0f;

    auto load_stage = [&](int s, int kt) {
        const int k0 = kt * BK;
        float* as = As + s * STAGE_F;
        float* bs = Bs + s * STAGE_F;
        cp_async16(smem_u32(as + row_c0 * ASTRIDE + kc0),
                   A + (size_t)(m0 + row_c0) * WID + k0 + kc0);
        cp_async16(smem_u32(as + row_c1 * ASTRIDE + kc1),
                   A + (size_t)(m0 + row_c1) * WID + k0 + kc1);
        cp_async16(smem_u32(bs + row_c0 * ASTRIDE + kc0),
                   B + (size_t)(n0 + row_c0) * WID + k0 + kc0);
        cp_async16(smem_u32(bs + row_c1 * ASTRIDE + kc1),
                   B + (size_t)(n0 + row_c1) * WID + k0 + kc1);
        CP_COMMIT();
    };

    #pragma unroll
    for (int s = 0; s < STAGES - 1; s++) load_stage(s, s);

    const int a_r = lane >> 2;          // 0..7
    const int a_k = lane & 3;           // 0..3

    for (int it = 0; it < NITER; it++) {
        CP_WAIT(STAGES - 2);
        __syncthreads();

        int nxt = it + STAGES - 1;
        if (nxt < NITER) load_stage(nxt & (STAGES - 1), nxt);

        const int buf = it & (STAGES - 1);
        const uint32_t* as = reinterpret_cast<const uint32_t*>(As + buf * STAGE_F);
        const uint32_t* bs = reinterpret_cast<const uint32_t*>(Bs + buf * STAGE_F);

        #pragma unroll
        for (int kk = 0; kk < 2; kk++) {
            const int kb = kk * 8;
            uint32_t af[4][4], bf[4][2];
            #pragma unroll
            for (int mi = 0; mi < 4; mi++) {
                int r0 = warp_m + mi * 16 + a_r;
                af[mi][0] = as[(r0    ) * ASTRIDE + kb + a_k    ];
                af[mi][1] = as[(r0 + 8) * ASTRIDE + kb + a_k    ];
                af[mi][2] = as[(r0    ) * ASTRIDE + kb + a_k + 4];
                af[mi][3] = as[(r0 + 8) * ASTRIDE + kb + a_k + 4];
            }
            #pragma unroll
            for (int ni = 0; ni < 4; ni++) {
                int n = warp_n + ni * 8 + a_r;
                bf[ni][0] = bs[n * ASTRIDE + kb + a_k    ];
                bf[ni][1] = bs[n * ASTRIDE + kb + a_k + 4];
            }
            #pragma unroll
            for (int mi = 0; mi < 4; mi++)
                #pragma unroll
                for (int ni = 0; ni < 4; ni++)
                    mma_tf32(c[mi][ni][0], c[mi][ni][1], c[mi][ni][2], c[mi][ni][3],
                             af[mi][0], af[mi][1], af[mi][2], af[mi][3],
                             bf[ni][0], bf[ni][1]);
        }
    }

    // epilogue: c0,c1 -> (row, col), (row, col+1); c2,c3 -> (row+8, ...)
    #pragma unroll
    for (int ni = 0; ni < 4; ni++) {
        const int col = n0 + warp_n + ni * 8 + (lane & 3) * 2;
        const float2 bv = *reinterpret_cast<const float2*>(bias + col);
        #pragma unroll
        for (int mi = 0; mi < 4; mi++) {
            const int row = m0 + warp_m + mi * 16 + (lane >> 2);
            #pragma unroll
            for (int h = 0; h < 2; h++) {          // h=0: row, h=1: row+8
                const size_t r = (size_t)(row + h * 8);
                float2 v;
                v.x = c[mi][ni][2 * h + 0] + bv.x;
                v.y = c[mi][ni][2 * h + 1] + bv.y;
                if (DO_GELU) {
                    v.x = tf32_rna(gelu_exact(v.x));
                    v.y = tf32_rna(gelu_exact(v.y));
                } else {
                    const float2 rx = *reinterpret_cast<const float2*>(resid + r * WID + col);
                    v.x += rx.x; v.y += rx.y;
                }
                *reinterpret_cast<float2*>(outp + r * WID + col) = v;
            }
        }
    }
}

// ---------------------------------------------------------------------------
// host side
// ---------------------------------------------------------------------------
extern "C" void kernel_launch(void* const* d_in, const int* in_sizes, int n_in,
                              void* d_out, int out_size) {
    const float* x     = (const float*)d_in[0];
    const float* gamma = (const float*)d_in[1];
    const float* beta  = (const float*)d_in[2];
    const float* w1    = (const float*)d_in[3];
    const float* b1    = (const float*)d_in[4];
    const float* w2    = (const float*)d_in[5];
    const float* b2    = (const float*)d_in[6];
    float* out = (float*)d_out;

    void *p_ln, *p_h, *p_w1, *p_w2;
    cudaGetSymbolAddress(&p_ln, g_ln);
    cudaGetSymbolAddress(&p_h,  g_h);
    cudaGetSymbolAddress(&p_w1, g_w1);
    cudaGetSymbolAddress(&p_w2, g_w2);

    const int smem_bytes = 2 * STAGES * STAGE_F * (int)sizeof(float);  // 81920
    cudaFuncSetAttribute(gemm_kernel<true>,
                         cudaFuncAttributeMaxDynamicSharedMemorySize, smem_bytes);
    cudaFuncSetAttribute(gemm_kernel<false>,
                         cudaFuncAttributeMaxDynamicSharedMemorySize, smem_bytes);

    rw_kernel<<<(WID * WID / 4) / 256, 256>>>(w1, (float*)p_w1);
    rw_kernel<<<(WID * WID / 4) / 256, 256>>>(w2, (float*)p_w2);
    ln_kernel<<<ROWS, 128>>>(x, gamma, beta, (float*)p_ln);

    dim3 grid(ROWS / BM, WID / BN);   // 128 x 8
    gemm_kernel<true ><<<grid, 256, smem_bytes>>>((const float*)p_ln, (const float*)p_w1,
                                                  b1, nullptr, (float*)p_h);
    gemm_kernel<false><<<grid, 256, smem_bytes>>>((const float*)p_h, (const float*)p_w2,
                                                  b2, x, out);
}

// round 4
// speedup vs baseline: 1.1817x; 1.1817x over previous
#include <cuda_runtime.h>
#include <cstdint>

// ---------------------------------------------------------------------------
// Residual MLP block, sm_103 baseline-PTX path (harness compiles at plain
// compute_103, so tcgen05 is unavailable; legacy HMMA path via mma.sync).
// GEMMs: mma.sync m16n8k8 tf32, cp.async 3-stage pipeline, warp tile 64x64.
// out = x + W2 @ gelu(W1 @ LN(x) + b1) + b2
// ---------------------------------------------------------------------------

#define ROWS   16384
#define WID    1024
#define BM     128
#define BN     256
#define BK     32
#define NITER  (WID / BK)        // 32
#define STAGES 3
#define ASTRIDE 36               // 32 + 4 pad: conflict-free fragment LDS, 16B aligned
#define ROWS_PER_STAGE (BM + BN)            // 384
#define STAGE_F (ROWS_PER_STAGE * ASTRIDE)  // 13824 floats
#define SMEM_BYTES (STAGES * STAGE_F * 4)   // 165888

// scratch (device globals: allocation-free per harness rules)
__device__ float g_ln[ROWS * WID];
__device__ float g_h [ROWS * WID];
__device__ float g_w1[WID * WID];
__device__ float g_w2[WID * WID];

// ---------------------------------------------------------------------------
static __device__ __forceinline__ uint32_t smem_u32(const void* p) {
    uint32_t a;
    asm("{ .reg .u64 t; cvta.to.shared.u64 t, %1; cvt.u32.u64 %0, t; }"
        : "=r"(a) : "l"(p));
    return a;
}

static __device__ __forceinline__ float tf32_rna(float f) {
    uint32_t r;
    asm("cvt.rna.tf32.f32 %0, %1;" : "=r"(r) : "f"(f));
    return __uint_as_float(r);
}

static __device__ __forceinline__ void cp_async16(uint32_t saddr, const void* g) {
    asm volatile("cp.async.ca.shared.global [%0], [%1], 16;"
                 :: "r"(saddr), "l"(g) : "memory");
}
#define CP_COMMIT()  asm volatile("cp.async.commit_group;" ::: "memory")
#define CP_WAIT(N)   asm volatile("cp.async.wait_group %0;" :: "n"(N) : "memory")

static __device__ __forceinline__ void mma_tf32(float& c0, float& c1, float& c2, float& c3,
                                                uint32_t a0, uint32_t a1, uint32_t a2, uint32_t a3,
                                                uint32_t b0, uint32_t b1) {
    asm volatile("mma.sync.aligned.m16n8k8.row.col.f32.tf32.tf32.f32 "
                 "{%0,%1,%2,%3}, {%4,%5,%6,%7}, {%8,%9}, {%0,%1,%2,%3};"
                 : "+f"(c0), "+f"(c1), "+f"(c2), "+f"(c3)
                 : "r"(a0), "r"(a1), "r"(a2), "r"(a3), "r"(b0), "r"(b1));
}

static __device__ __forceinline__ float gelu_exact(float v) {
    return 0.5f * v * (1.0f + erff(v * 0.7071067811865476f));
}

// ---------------------------------------------------------------------------
__global__ void rw_kernel(const float* __restrict__ w, float* __restrict__ o) {
    int i = blockIdx.x * blockDim.x + threadIdx.x;   // over float4
    float4 v = reinterpret_cast<const float4*>(w)[i];
    v.x = tf32_rna(v.x); v.y = tf32_rna(v.y); v.z = tf32_rna(v.z); v.w = tf32_rna(v.w);
    reinterpret_cast<float4*>(o)[i] = v;
}

// ---------------------------------------------------------------------------
__global__ void ln_kernel(const float* __restrict__ x, const float* __restrict__ g,
                          const float* __restrict__ b, float* __restrict__ o) {
    int row = blockIdx.x;
    int t   = threadIdx.x;
    int wid = t >> 5, lid = t & 31;
    const float4* xr = reinterpret_cast<const float4*>(x + (size_t)row * WID);
    float4 v0 = xr[t], v1 = xr[t + 128];

    float s = v0.x + v0.y + v0.z + v0.w + v1.x + v1.y + v1.z + v1.w;
    float q = v0.x*v0.x + v0.y*v0.y + v0.z*v0.z + v0.w*v0.w
            + v1.x*v1.x + v1.y*v1.y + v1.z*v1.z + v1.w*v1.w;
    #pragma unroll
    for (int off = 16; off > 0; off >>= 1) {
        s += __shfl_xor_sync(0xffffffffu, s, off);
        q += __shfl_xor_sync(0xffffffffu, q, off);
    }
    __shared__ float rs_[4], rq_[4];
    if (lid == 0) { rs_[wid] = s; rq_[wid] = q; }
    __syncthreads();
    float S  = rs_[0] + rs_[1] + rs_[2] + rs_[3];
    float Q  = rq_[0] + rq_[1] + rq_[2] + rq_[3];
    float mu = S * (1.0f / WID);
    float var = Q * (1.0f / WID) - mu * mu;
    float r  = rsqrtf(var + 1e-5f);

    const float4* gr = reinterpret_cast<const float4*>(g);
    const float4* br = reinterpret_cast<const float4*>(b);
    float4 g0 = gr[t], g1 = gr[t + 128], b0 = br[t], b1 = br[t + 128];
    float4 o0, o1;
    o0.x = tf32_rna((v0.x - mu) * r * g0.x + b0.x);
    o0.y = tf32_rna((v0.y - mu) * r * g0.y + b0.y);
    o0.z = tf32_rna((v0.z - mu) * r * g0.z + b0.z);
    o0.w = tf32_rna((v0.w - mu) * r * g0.w + b0.w);
    o1.x = tf32_rna((v1.x - mu) * r * g1.x + b1.x);
    o1.y = tf32_rna((v1.y - mu) * r * g1.y + b1.y);
    o1.z = tf32_rna((v1.z - mu) * r * g1.z + b1.z);
    o1.w = tf32_rna((v1.w - mu) * r * g1.w + b1.w);
    float4* orow = reinterpret_cast<float4*>(o + (size_t)row * WID);
    orow[t] = o0; orow[t + 128] = o1;
}

// ---------------------------------------------------------------------------
// GEMM: block 128x256, 8 warps (2m x 4n), warp tile 64x64.
// A[BM,K] @ B[BN,K]^T, fp32 K-major operands pre-rounded to tf32.
// ---------------------------------------------------------------------------
template <bool DO_GELU>
__global__ void __launch_bounds__(256, 1) gemm_kernel(
    const float* __restrict__ A, const float* __restrict__ B,
    const float* __restrict__ bias, const float* __restrict__ resid,
    float* __restrict__ outp)
{
    extern __shared__ float smem[];

    const int tid    = threadIdx.x;
    const int lane   = tid & 31;
    const int w      = tid >> 5;
    const int warp_m = (w & 1) * 64;
    const int warp_n = (w >> 1) * 64;
    const int m0     = blockIdx.x * BM;
    const int n0     = blockIdx.y * BN;

    float c[4][8][4];
    #pragma unroll
    for (int mi = 0; mi < 4; mi++)
        #pragma unroll
        for (int ni = 0; ni < 8; ni++)
            #pragma unroll
            for (int r = 0; r < 4; r++) c[mi][ni][r] = 0.0f;

    // cp.async: 384 rows x 32 floats = 3072 x 16B chunks / 256 threads = 12 each.
    // chunk c: row = c>>3 (0..383), kcol = (c&7)*4. rows 0..127 -> A, 128..383 -> B.
    auto load_stage = [&](int s, int kt) {
        const int k0 = kt * BK;
        float* st = smem + s * STAGE_F;
        #pragma unroll
        for (int i = 0; i < 12; i++) {
            const int ch   = tid + i * 256;
            const int row  = ch >> 3;
            const int kcol = (ch & 7) * 4;
            const float* src = (row < BM)
                ? (A + (size_t)(m0 + row) * WID + k0 + kcol)
                : (B + (size_t)(n0 + row - BM) * WID + k0 + kcol);
            cp_async16(smem_u32(st + row * ASTRIDE + kcol), src);
        }
        CP_COMMIT();
    };

    #pragma unroll
    for (int s = 0; s < STAGES - 1; s++) load_stage(s, s);

    const int a_r = lane >> 2;          // 0..7
    const int a_k = lane & 3;           // 0..3

    for (int it = 0; it < NITER; it++) {
        CP_WAIT(STAGES - 2);
        __syncthreads();

        const int nxt = it + STAGES - 1;
        if (nxt < NITER) load_stage(nxt % STAGES, nxt);

        const int buf = it % STAGES;
        const uint32_t* as = reinterpret_cast<const uint32_t*>(smem + buf * STAGE_F);
        const uint32_t* bs = as + BM * ASTRIDE;

        #pragma unroll
        for (int kk = 0; kk < 4; kk++) {
            const int kb = kk * 8;
            uint32_t af[4][4], bf[8][2];
            #pragma unroll
            for (int mi = 0; mi < 4; mi++) {
                const int r0 = warp_m + mi * 16 + a_r;
                af[mi][0] = as[(r0    ) * ASTRIDE + kb + a_k    ];
                af[mi][1] = as[(r0 + 8) * ASTRIDE + kb + a_k    ];
                af[mi][2] = as[(r0    ) * ASTRIDE + kb + a_k + 4];
                af[mi][3] = as[(r0 + 8) * ASTRIDE + kb + a_k + 4];
            }
            #pragma unroll
            for (int ni = 0; ni < 8; ni++) {
                const int n = warp_n + ni * 8 + a_r;
                bf[ni][0] = bs[n * ASTRIDE + kb + a_k    ];
                bf[ni][1] = bs[n * ASTRIDE + kb + a_k + 4];
            }
            #pragma unroll
            for (int mi = 0; mi < 4; mi++)
                #pragma unroll
                for (int ni = 0; ni < 8; ni++)
                    mma_tf32(c[mi][ni][0], c[mi][ni][1], c[mi][ni][2], c[mi][ni][3],
                             af[mi][0], af[mi][1], af[mi][2], af[mi][3],
                             bf[ni][0], bf[ni][1]);
        }
    }

    // epilogue
    #pragma unroll
    for (int ni = 0; ni < 8; ni++) {
        const int col = n0 + warp_n + ni * 8 + (lane & 3) * 2;
        const float2 bv = *reinterpret_cast<const float2*>(bias + col);
        #pragma unroll
        for (int mi = 0; mi < 4; mi++) {
            const int row = m0 + warp_m + mi * 16 + (lane >> 2);
            #pragma unroll
            for (int h = 0; h < 2; h++) {
                const size_t r = (size_t)(row + h * 8);
                float2 v;
                v.x = c[mi][ni][2 * h + 0] + bv.x;
                v.y = c[mi][ni][2 * h + 1] + bv.y;
                if (DO_GELU) {
                    v.x = tf32_rna(gelu_exact(v.x));
                    v.y = tf32_rna(gelu_exact(v.y));
                } else {
                    const float2 rx = *reinterpret_cast<const float2*>(resid + r * WID + col);
                    v.x += rx.x; v.y += rx.y;
                }
                *reinterpret_cast<float2*>(outp + r * WID + col) = v;
            }
        }
    }
}

// ---------------------------------------------------------------------------
extern "C" void kernel_launch(void* const* d_in, const int* in_sizes, int n_in,
                              void* d_out, int out_size) {
    const float* x     = (const float*)d_in[0];
    const float* gamma = (const float*)d_in[1];
    const float* beta  = (const float*)d_in[2];
    const float* w1    = (const float*)d_in[3];
    const float* b1    = (const float*)d_in[4];
    const float* w2    = (const float*)d_in[5];
    const float* b2    = (const float*)d_in[6];
    float* out = (float*)d_out;

    void *p_ln, *p_h, *p_w1, *p_w2;
    cudaGetSymbolAddress(&p_ln, g_ln);
    cudaGetSymbolAddress(&p_h,  g_h);
    cudaGetSymbolAddress(&p_w1, g_w1);
    cudaGetSymbolAddress(&p_w2, g_w2);

    cudaFuncSetAttribute(gemm_kernel<true>,
                         cudaFuncAttributeMaxDynamicSharedMemorySize, SMEM_BYTES);
    cudaFuncSetAttribute(gemm_kernel<false>,
                         cudaFuncAttributeMaxDynamicSharedMemorySize, SMEM_BYTES);

    rw_kernel<<<(WID * WID / 4) / 256, 256>>>(w1, (float*)p_w1);
    rw_kernel<<<(WID * WID / 4) / 256, 256>>>(w2, (float*)p_w2);
    ln_kernel<<<ROWS, 128>>>(x, gamma, beta, (float*)p_ln);

    dim3 grid(ROWS / BM, WID / BN);   // 128 x 4 = 512 CTAs
    gemm_kernel<true ><<<grid, 256, SMEM_BYTES>>>((const float*)p_ln, (const float*)p_w1,
                                                  b1, nullptr, (float*)p_h);
    gemm_kernel<false><<<grid, 256, SMEM_BYTES>>>((const float*)p_h, (const float*)p_w2,
                                                  b2, x, out);
}